// round 2
// baseline (speedup 1.0000x reference)
#include <cuda_runtime.h>
#include <math.h>

#define BATCH  16384
#define IN_F   512
#define OUT_F  512
#define NB     9              // silu + 8 spline bases per input feature
#define KDIM   (IN_F * NB)    // 4608
#define NGRID  12             // grid points per feature

// Scratch (allocation-free rule: __device__ globals)
__device__ float g_A[(size_t)BATCH * KDIM];   // expanded activations, row-major [B][K]
__device__ float g_W[(size_t)OUT_F * KDIM];   // packed weights, row-major [O][K]

// ---------------------------------------------------------------------------
// Kernel 1: expansion. One thread per (b, i): silu + cubic B-spline bases.
// ---------------------------------------------------------------------------
__global__ void expand_kernel(const float* __restrict__ x,
                              const float* __restrict__ grid)
{
    int idx = blockIdx.x * blockDim.x + threadIdx.x;
    if (idx >= BATCH * IN_F) return;
    int i = idx & (IN_F - 1);      // IN_F = 512 (pow2)

    float xv = x[idx];

    // silu
    float s = xv / (1.0f + __expf(-xv));

    // load this feature's knot vector (12 values)
    const float* g = grid + i * NGRID;
    float gv[NGRID];
#pragma unroll
    for (int t = 0; t < NGRID; t++) gv[t] = __ldg(g + t);

    // Cox-de Boor, order 0 -> 3
    float bs[11];
#pragma unroll
    for (int j = 0; j < 11; j++)
        bs[j] = (xv >= gv[j] && xv < gv[j + 1]) ? 1.0f : 0.0f;

#pragma unroll
    for (int k = 1; k <= 3; k++) {
#pragma unroll
        for (int j = 0; j < 11 - 1; j++) {
            if (j < 11 - k) {
                float left  = (xv - gv[j])         * __fdividef(1.0f, gv[j + k]     - gv[j]);
                float right = (gv[j + k + 1] - xv) * __fdividef(1.0f, gv[j + k + 1] - gv[j + 1]);
                bs[j] = left * bs[j] + right * bs[j + 1];
            }
        }
    }

    float* out = g_A + (size_t)idx * NB;   // idx*NB == b*KDIM + i*NB  (contiguous layout)
    out[0] = s;
#pragma unroll
    for (int j = 0; j < 8; j++) out[1 + j] = bs[j];
}

// ---------------------------------------------------------------------------
// Kernel 2: pack weights. One thread per (o, i).
// ---------------------------------------------------------------------------
__global__ void pack_w_kernel(const float* __restrict__ bw,
                              const float* __restrict__ sw,
                              const float* __restrict__ sc)
{
    int idx = blockIdx.x * blockDim.x + threadIdx.x;
    if (idx >= OUT_F * IN_F) return;

    float scale = sc[idx];
    float* w = g_W + (size_t)idx * NB;     // idx*NB == o*KDIM + i*NB
    w[0] = bw[idx];
    const float* s = sw + (size_t)idx * 8;
#pragma unroll
    for (int j = 0; j < 8; j++) w[1 + j] = s[j] * scale;
}

// ---------------------------------------------------------------------------
// Kernel 3: C[B][OUT] = A @ W^T.  128x128x8 tiled sgemm, 256 thr, 8x8 microtile,
// double-buffered SMEM with +4 padding (conflict-free transposed staging).
// All dims divide evenly (16384/128, 512/128, 4608/8) — no guards needed.
// ---------------------------------------------------------------------------
#define BM 128
#define BN 128
#define BK 8
#define TM 8
#define TN 8
#define LDS_PAD 4
#define LDS_W (BM + LDS_PAD)   // 132 floats; 132*4=528 bytes, 16B-aligned rows

__global__ __launch_bounds__(256, 2)
void sgemm_kernel(float* __restrict__ C)
{
    __shared__ float As[2][BK][LDS_W];
    __shared__ float Bs[2][BK][LDS_W];

    const int tid = threadIdx.x;
    const int tx = tid & 15;    // N direction (16)
    const int ty = tid >> 4;    // M direction (16)

    const float* Ab = g_A + (size_t)blockIdx.y * BM * KDIM;
    const float* Wb = g_W + (size_t)blockIdx.x * BN * KDIM;

    // each thread loads one float4 of A and one of W per K-tile
    const int ldRow = tid >> 1;          // 0..127
    const int ldCol = (tid & 1) * 4;     // 0 or 4

    const float* aPtr = Ab + (size_t)ldRow * KDIM + ldCol;
    const float* wPtr = Wb + (size_t)ldRow * KDIM + ldCol;

    float acc[TM][TN] = {};
    float regM[TM], regN[TN];

    const int NT = KDIM / BK;   // 576 tiles

    // Preload tile 0 into buffer 0
    {
        float4 av = *reinterpret_cast<const float4*>(aPtr);
        float4 wv = *reinterpret_cast<const float4*>(wPtr);
        As[0][ldCol + 0][ldRow] = av.x;
        As[0][ldCol + 1][ldRow] = av.y;
        As[0][ldCol + 2][ldRow] = av.z;
        As[0][ldCol + 3][ldRow] = av.w;
        Bs[0][ldCol + 0][ldRow] = wv.x;
        Bs[0][ldCol + 1][ldRow] = wv.y;
        Bs[0][ldCol + 2][ldRow] = wv.z;
        Bs[0][ldCol + 3][ldRow] = wv.w;
    }
    __syncthreads();

    for (int t = 0; t < NT; t++) {
        const int cur = t & 1;
        const int nxt = cur ^ 1;

        float4 av, wv;
        const bool more = (t + 1 < NT);
        if (more) {
            av = *reinterpret_cast<const float4*>(aPtr + (size_t)(t + 1) * BK);
            wv = *reinterpret_cast<const float4*>(wPtr + (size_t)(t + 1) * BK);
        }

#pragma unroll
        for (int k = 0; k < BK; k++) {
            float4 m0 = *reinterpret_cast<const float4*>(&As[cur][k][ty * TM]);
            float4 m1 = *reinterpret_cast<const float4*>(&As[cur][k][ty * TM + 4]);
            float4 n0 = *reinterpret_cast<const float4*>(&Bs[cur][k][tx * TN]);
            float4 n1 = *reinterpret_cast<const float4*>(&Bs[cur][k][tx * TN + 4]);
            regM[0] = m0.x; regM[1] = m0.y; regM[2] = m0.z; regM[3] = m0.w;
            regM[4] = m1.x; regM[5] = m1.y; regM[6] = m1.z; regM[7] = m1.w;
            regN[0] = n0.x; regN[1] = n0.y; regN[2] = n0.z; regN[3] = n0.w;
            regN[4] = n1.x; regN[5] = n1.y; regN[6] = n1.z; regN[7] = n1.w;
#pragma unroll
            for (int m = 0; m < TM; m++)
#pragma unroll
                for (int n = 0; n < TN; n++)
                    acc[m][n] += regM[m] * regN[n];
        }

        if (more) {
            As[nxt][ldCol + 0][ldRow] = av.x;
            As[nxt][ldCol + 1][ldRow] = av.y;
            As[nxt][ldCol + 2][ldRow] = av.z;
            As[nxt][ldCol + 3][ldRow] = av.w;
            Bs[nxt][ldCol + 0][ldRow] = wv.x;
            Bs[nxt][ldCol + 1][ldRow] = wv.y;
            Bs[nxt][ldCol + 2][ldRow] = wv.z;
            Bs[nxt][ldCol + 3][ldRow] = wv.w;
        }
        __syncthreads();
    }

    float* Cb = C + (size_t)(blockIdx.y * BM + ty * TM) * OUT_F
                  + blockIdx.x * BN + tx * TN;
#pragma unroll
    for (int m = 0; m < TM; m++) {
        float4 v0 = make_float4(acc[m][0], acc[m][1], acc[m][2], acc[m][3]);
        float4 v1 = make_float4(acc[m][4], acc[m][5], acc[m][6], acc[m][7]);
        *reinterpret_cast<float4*>(Cb + (size_t)m * OUT_F)     = v0;
        *reinterpret_cast<float4*>(Cb + (size_t)m * OUT_F + 4) = v1;
    }
}

// ---------------------------------------------------------------------------
// Launch
// ---------------------------------------------------------------------------
extern "C" void kernel_launch(void* const* d_in, const int* in_sizes, int n_in,
                              void* d_out, int out_size)
{
    const float* x   = (const float*)d_in[0];   // [16384, 512]
    const float* bw  = (const float*)d_in[1];   // [512, 512]
    const float* sw  = (const float*)d_in[2];   // [512, 512, 8]
    const float* sc  = (const float*)d_in[3];   // [512, 512]
    const float* grd = (const float*)d_in[4];   // [512, 12]
    float* out = (float*)d_out;                 // [16384, 512]

    (void)in_sizes; (void)n_in; (void)out_size;

    expand_kernel<<<(BATCH * IN_F + 255) / 256, 256>>>(x, grd);
    pack_w_kernel<<<(OUT_F * IN_F + 255) / 256, 256>>>(bw, sw, sc);

    dim3 grid(OUT_F / BN, BATCH / BM);   // (4, 128)
    sgemm_kernel<<<grid, 256>>>(out);
}

// round 4
// speedup vs baseline: 1.8216x; 1.8216x over previous
#include <cuda_runtime.h>
#include <cuda_bf16.h>
#include <stdint.h>

#define BATCH  16384
#define IN_F   512
#define OUT_F  512
#define NB     9
#define KDIM   (IN_F * NB)     // 4608
#define NGRID  12

// ---- scratch (__device__ globals; allocation-free rule) ----
__device__ __nv_bfloat16 g_Ah[(size_t)BATCH * KDIM];
__device__ __nv_bfloat16 g_Al[(size_t)BATCH * KDIM];
__device__ __nv_bfloat16 g_Wh[(size_t)OUT_F * KDIM];
__device__ __nv_bfloat16 g_Wl[(size_t)OUT_F * KDIM];

// ---------------------------------------------------------------------------
// Kernel 1: expansion -> split bf16 (hi, lo). One block per batch row.
// ---------------------------------------------------------------------------
__global__ __launch_bounds__(512)
void expand_kernel(const float* __restrict__ x, const float* __restrict__ grid)
{
    __shared__ __nv_bfloat16 sh[KDIM];   // 9216 B
    __shared__ __nv_bfloat16 sl[KDIM];

    const int b = blockIdx.x;
    const int i = threadIdx.x;

    float xv = x[(size_t)b * IN_F + i];
    float s  = xv / (1.0f + __expf(-xv));

    const float* g = grid + i * NGRID;
    float gv[NGRID];
#pragma unroll
    for (int t = 0; t < NGRID; t++) gv[t] = __ldg(g + t);

    float bs[11];
#pragma unroll
    for (int j = 0; j < 11; j++)
        bs[j] = (xv >= gv[j] && xv < gv[j + 1]) ? 1.0f : 0.0f;

#pragma unroll
    for (int k = 1; k <= 3; k++) {
#pragma unroll
        for (int j = 0; j < 10; j++) {
            if (j < 11 - k) {
                float left  = (xv - gv[j])         * __fdividef(1.0f, gv[j + k]     - gv[j]);
                float right = (gv[j + k + 1] - xv) * __fdividef(1.0f, gv[j + k + 1] - gv[j + 1]);
                bs[j] = left * bs[j] + right * bs[j + 1];
            }
        }
    }

    float v[NB];
    v[0] = s;
#pragma unroll
    for (int j = 0; j < 8; j++) v[1 + j] = bs[j];

#pragma unroll
    for (int j = 0; j < NB; j++) {
        __nv_bfloat16 h = __float2bfloat16(v[j]);
        sh[i * NB + j] = h;
        sl[i * NB + j] = __float2bfloat16(v[j] - __bfloat162float(h));
    }
    __syncthreads();

    // vectorized copy to global (576 float4 chunks per matrix)
    float4* dh = reinterpret_cast<float4*>(g_Ah + (size_t)b * KDIM);
    float4* dl = reinterpret_cast<float4*>(g_Al + (size_t)b * KDIM);
    const float4* s4h = reinterpret_cast<const float4*>(sh);
    const float4* s4l = reinterpret_cast<const float4*>(sl);
#pragma unroll
    for (int c = threadIdx.x; c < KDIM * 2 / 16; c += 512) {
        dh[c] = s4h[c];
        dl[c] = s4l[c];
    }
}

// ---------------------------------------------------------------------------
// Kernel 2: pack weights -> split bf16. One block per output row.
// ---------------------------------------------------------------------------
__global__ __launch_bounds__(512)
void pack_w_kernel(const float* __restrict__ bw,
                   const float* __restrict__ sw,
                   const float* __restrict__ sc)
{
    __shared__ __nv_bfloat16 sh[KDIM];
    __shared__ __nv_bfloat16 sl[KDIM];

    const int o = blockIdx.x;
    const int i = threadIdx.x;
    const size_t oi = (size_t)o * IN_F + i;

    float scale = sc[oi];
    float v[NB];
    v[0] = bw[oi];
    const float* swp = sw + oi * 8;
#pragma unroll
    for (int j = 0; j < 8; j++) v[1 + j] = swp[j] * scale;

#pragma unroll
    for (int j = 0; j < NB; j++) {
        __nv_bfloat16 h = __float2bfloat16(v[j]);
        sh[i * NB + j] = h;
        sl[i * NB + j] = __float2bfloat16(v[j] - __bfloat162float(h));
    }
    __syncthreads();

    float4* dh = reinterpret_cast<float4*>(g_Wh + (size_t)o * KDIM);
    float4* dl = reinterpret_cast<float4*>(g_Wl + (size_t)o * KDIM);
    const float4* s4h = reinterpret_cast<const float4*>(sh);
    const float4* s4l = reinterpret_cast<const float4*>(sl);
#pragma unroll
    for (int c = threadIdx.x; c < KDIM * 2 / 16; c += 512) {
        dh[c] = s4h[c];
        dl[c] = s4l[c];
    }
}

// ---------------------------------------------------------------------------
// Kernel 3: bf16 3-pass tensor-core GEMM.  C = Ah*Wh + Ah*Wl + Al*Wh (fp32 acc)
// 128x128 CTA tile, BK=16, cp.async double buffer, mma.sync.m16n8k16.
// ---------------------------------------------------------------------------
#define BM 128
#define BN 128
#define BKH 16
#define NT (KDIM / BKH)        // 288
#define LDT 24                 // padded row length in halves (48 B, 16B-aligned)

__device__ __forceinline__ void cp_async16(uint32_t dst, const void* src) {
    asm volatile("cp.async.cg.shared.global [%0], [%1], 16;\n" :: "r"(dst), "l"(src));
}
__device__ __forceinline__ void ldm_x4(uint32_t* r, uint32_t addr) {
    asm volatile("ldmatrix.sync.aligned.m8n8.x4.shared.b16 {%0,%1,%2,%3}, [%4];\n"
                 : "=r"(r[0]), "=r"(r[1]), "=r"(r[2]), "=r"(r[3]) : "r"(addr));
}
__device__ __forceinline__ void mma16816(float* c, const uint32_t* a, const uint32_t* b) {
    asm volatile("mma.sync.aligned.m16n8k16.row.col.f32.bf16.bf16.f32 "
                 "{%0,%1,%2,%3}, {%4,%5,%6,%7}, {%8,%9}, {%0,%1,%2,%3};\n"
                 : "+f"(c[0]), "+f"(c[1]), "+f"(c[2]), "+f"(c[3])
                 : "r"(a[0]), "r"(a[1]), "r"(a[2]), "r"(a[3]), "r"(b[0]), "r"(b[1]));
}

__global__ __launch_bounds__(256)
void gemm_kernel(float* __restrict__ C)
{
    // [stage][hi/lo][row*LDT + col]   total = 2*2*(128*24)*2B * 2(A,B) = 49152 B
    __shared__ __nv_bfloat16 sA[2][2][BM * LDT];
    __shared__ __nv_bfloat16 sB[2][2][BN * LDT];

    const int tid  = threadIdx.x;
    const int lane = tid & 31;
    const int wid  = tid >> 5;
    const int wm   = wid & 1;    // 2 warps along M (64 rows each)
    const int wn   = wid >> 1;   // 4 warps along N (32 cols each)

    // ---- cp.async source/dest setup: thread -> (row, 8-half chunk) ----
    const int ldRow = tid >> 1;          // 0..127
    const int ldCh  = tid & 1;           // 0..1

    const __nv_bfloat16* gAh = g_Ah + ((size_t)(blockIdx.y * BM + ldRow)) * KDIM + ldCh * 8;
    const __nv_bfloat16* gAl = g_Al + ((size_t)(blockIdx.y * BM + ldRow)) * KDIM + ldCh * 8;
    const __nv_bfloat16* gWh = g_Wh + ((size_t)(blockIdx.x * BN + ldRow)) * KDIM + ldCh * 8;
    const __nv_bfloat16* gWl = g_Wl + ((size_t)(blockIdx.x * BN + ldRow)) * KDIM + ldCh * 8;

    const uint32_t dOff = (uint32_t)((ldRow * LDT + ldCh * 8) * 2);
    const uint32_t sAh0 = (uint32_t)__cvta_generic_to_shared(&sA[0][0][0]);
    const uint32_t sAl0 = (uint32_t)__cvta_generic_to_shared(&sA[0][1][0]);
    const uint32_t sBh0 = (uint32_t)__cvta_generic_to_shared(&sB[0][0][0]);
    const uint32_t sBl0 = (uint32_t)__cvta_generic_to_shared(&sB[0][1][0]);
    const uint32_t stgA = (uint32_t)(sizeof(__nv_bfloat16) * 2 * BM * LDT); // stage stride
    const uint32_t stgB = (uint32_t)(sizeof(__nv_bfloat16) * 2 * BN * LDT);

    // ---- ldmatrix address setup ----
    const int aRow = wm * 64 + (lane & 15);
    const int aCol = (lane >> 4) << 3;
    const int bRow = wn * 32 + ((lane >> 4) << 3) + (lane & 7);
    const int bCol = ((lane >> 3) & 1) << 3;

    float acc[4][4][4];
#pragma unroll
    for (int m = 0; m < 4; m++)
#pragma unroll
        for (int n = 0; n < 4; n++)
#pragma unroll
            for (int r = 0; r < 4; r++) acc[m][n][r] = 0.0f;

    // ---- prime stage 0 ----
    {
        cp_async16(sAh0 + dOff, gAh);
        cp_async16(sAl0 + dOff, gAl);
        cp_async16(sBh0 + dOff, gWh);
        cp_async16(sBl0 + dOff, gWl);
        asm volatile("cp.async.commit_group;\n");
    }

    for (int t = 0; t < NT; t++) {
        const int cur = t & 1;
        if (t + 1 < NT) {
            const size_t go = (size_t)(t + 1) * BKH;
            cp_async16(sAh0 + (cur ^ 1) * stgA + dOff, gAh + go);
            cp_async16(sAl0 + (cur ^ 1) * stgA + dOff, gAl + go);
            cp_async16(sBh0 + (cur ^ 1) * stgB + dOff, gWh + go);
            cp_async16(sBl0 + (cur ^ 1) * stgB + dOff, gWl + go);
            asm volatile("cp.async.commit_group;\n");
            asm volatile("cp.async.wait_group 1;\n");
        } else {
            asm volatile("cp.async.wait_group 0;\n");
        }
        __syncthreads();

        // load fragments
        uint32_t ah[4][4], al[4][4], bh[4][2], bl[4][2];
#pragma unroll
        for (int mt = 0; mt < 4; mt++) {
            uint32_t addr = (uint32_t)__cvta_generic_to_shared(
                &sA[cur][0][(aRow + mt * 16) * LDT + aCol]);
            ldm_x4(ah[mt], addr);
            addr = (uint32_t)__cvta_generic_to_shared(
                &sA[cur][1][(aRow + mt * 16) * LDT + aCol]);
            ldm_x4(al[mt], addr);
        }
#pragma unroll
        for (int p = 0; p < 2; p++) {
            uint32_t r[4];
            uint32_t addr = (uint32_t)__cvta_generic_to_shared(
                &sB[cur][0][(bRow + p * 16) * LDT + bCol]);
            ldm_x4(r, addr);
            bh[2 * p][0] = r[0]; bh[2 * p][1] = r[1];
            bh[2 * p + 1][0] = r[2]; bh[2 * p + 1][1] = r[3];
            addr = (uint32_t)__cvta_generic_to_shared(
                &sB[cur][1][(bRow + p * 16) * LDT + bCol]);
            ldm_x4(r, addr);
            bl[2 * p][0] = r[0]; bl[2 * p][1] = r[1];
            bl[2 * p + 1][0] = r[2]; bl[2 * p + 1][1] = r[3];
        }

#pragma unroll
        for (int mt = 0; mt < 4; mt++)
#pragma unroll
            for (int nt = 0; nt < 4; nt++) {
                mma16816(acc[mt][nt], ah[mt], bh[nt]);
                mma16816(acc[mt][nt], ah[mt], bl[nt]);
                mma16816(acc[mt][nt], al[mt], bh[nt]);
            }

        __syncthreads();
    }

    // ---- epilogue ----
    const int rBase = blockIdx.y * BM + wm * 64 + (lane >> 2);
    const int cBase = blockIdx.x * BN + wn * 32 + (lane & 3) * 2;
#pragma unroll
    for (int mt = 0; mt < 4; mt++)
#pragma unroll
        for (int nt = 0; nt < 4; nt++) {
            float* p0 = C + (size_t)(rBase + mt * 16) * OUT_F + cBase + nt * 8;
            float* p1 = C + (size_t)(rBase + mt * 16 + 8) * OUT_F + cBase + nt * 8;
            *reinterpret_cast<float2*>(p0) = make_float2(acc[mt][nt][0], acc[mt][nt][1]);
            *reinterpret_cast<float2*>(p1) = make_float2(acc[mt][nt][2], acc[mt][nt][3]);
        }
}

// ---------------------------------------------------------------------------
// Launch
// ---------------------------------------------------------------------------
extern "C" void kernel_launch(void* const* d_in, const int* in_sizes, int n_in,
                              void* d_out, int out_size)
{
    const float* x   = (const float*)d_in[0];
    const float* bw  = (const float*)d_in[1];
    const float* sw  = (const float*)d_in[2];
    const float* sc  = (const float*)d_in[3];
    const float* grd = (const float*)d_in[4];
    float* out = (float*)d_out;

    (void)in_sizes; (void)n_in; (void)out_size;

    expand_kernel<<<BATCH, 512>>>(x, grd);
    pack_w_kernel<<<OUT_F, 512>>>(bw, sw, sc);

    dim3 grid(OUT_F / BN, BATCH / BM);   // (4, 128)
    gemm_kernel<<<grid, 256>>>(out);
}